// round 12
// baseline (speedup 1.0000x reference)
#include <cuda_runtime.h>
#include <cuda_bf16.h>
#include <cstdint>

#define IN_F     4096
#define OUT_F    11008
#define MROWS    32
#define GRP      128
#define KSPLIT   8
#define KPER     (IN_F / KSPLIT)          // 512
#define STAGE_K  16
#define NSTAGES  (KPER / STAGE_K)         // 32
#define NBUF     4
#define NTILE    256
#define CTAS_COL (OUT_F / NTILE)          // 43
#define THREADS  256

#define XROW_B   272                      // x row: 256B bf16 + 16B pad (ldmatrix conflict-free)
#define XS_BYTES (MROWS * XROW_B)         // 8704
#define WROW_W   260                      // 256 int32 (1KB) + 4 pad words
#define WROW_B   (WROW_W * 4)             // 1040
#define WSTAGE_B (STAGE_K * WROW_B)       // 16640
#define SM_WS    XS_BYTES
#define SM_TOTAL (SM_WS + NBUF * WSTAGE_B)   // 75264

__device__ __forceinline__ float bfr(float v) {
    return __bfloat162float(__float2bfloat16(v));
}

__device__ __forceinline__ uint32_t pack_bf16x2(float hi, float lo) {
    uint32_t r;
    asm("cvt.rn.bf16x2.f32 %0, %1, %2;" : "=r"(r) : "f"(hi), "f"(lo));
    return r;
}

// HMMA with zero C: d = A*B
__device__ __forceinline__ void hmma0(float d[4], const uint32_t a[4],
                                      uint32_t b0, uint32_t b1) {
    asm volatile(
        "mma.sync.aligned.m16n8k16.row.col.f32.bf16.bf16.f32 "
        "{%0,%1,%2,%3}, {%4,%5,%6,%7}, {%8,%9}, {%10,%10,%10,%10};"
        : "=f"(d[0]), "=f"(d[1]), "=f"(d[2]), "=f"(d[3])
        : "r"(a[0]), "r"(a[1]), "r"(a[2]), "r"(a[3]), "r"(b0), "r"(b1),
          "f"(0.0f));
}

// ---------------------------------------------------------------------------
__global__ void init_out_kernel(const float* __restrict__ bias,
                                float* __restrict__ out)
{
    int o = blockIdx.x * blockDim.x + threadIdx.x;
    if (o < OUT_F) {
        float b = bfr(bias[o]);
        #pragma unroll
        for (int s = 0; s < MROWS; s++)
            out[(size_t)s * OUT_F + o] = b;
    }
}

// ---------------------------------------------------------------------------
// Per CTA: 256 output cols x 512 K in 32 stages of 16 k-rows (one k16-step).
// Each k-row weight read is 1KB CONTIGUOUS (one HBM page) via cp.async.cg
// into a 4-buffer ring (3 stages in flight). B converts on-read ((qw-qz) is
// 5-bit, bf16-exact); scale applied per k-step via fp32 fma (exact class).
// Warp w owns local cols [32w, 32w+32) = 4 n8 fragments.
// ---------------------------------------------------------------------------
__global__ void __launch_bounds__(THREADS)
qmain(const float* __restrict__ x, const int* __restrict__ qweight,
      const int* __restrict__ qzeros, const float* __restrict__ scales,
      float* __restrict__ out)
{
    extern __shared__ __align__(16) uint8_t smem[];
    uint32_t sb;
    asm("{ .reg .u64 t; cvta.to.shared.u64 t, %1; cvt.u32.u64 %0, t; }"
        : "=r"(sb) : "l"(smem));
    const uint32_t xs_b = sb;
    const uint32_t ws_b = sb + SM_WS;

    const int tid   = threadIdx.x;
    const int w     = tid >> 5;            // 0..7
    const int l     = tid & 31;
    const int bx    = blockIdx.x;
    const int ctile = bx % CTAS_COL;
    const int kq    = bx / CTAS_COL;
    const int o0    = ctile * NTILE;
    const int k0    = kq * KPER;

    const int gid = l >> 2;
    const int tig = l & 3;
    const int cc  = o0 + w * 32 + 2 * tig;             // C col base; tiles at +8t

    const uint32_t a_lane_off = (uint32_t)(l & 15) * XROW_B + (uint32_t)(l >> 4) * 16;
    // B base: row 2tig, local col 32w+gid; per t add 8 cols (32B)
    const uint32_t b_off = (uint32_t)(2 * tig) * WROW_B + (uint32_t)(w * 32 + gid) * 4;

    // cp.async mapping: 4 ops/thread; row = tid>>6 (+4j), seg = tid&63 (16B)
    const int cp_row0 = tid >> 6;
    const int cp_seg  = tid & 63;

    float ct[2][4][4];
    #pragma unroll
    for (int mi = 0; mi < 2; mi++)
        #pragma unroll
        for (int t = 0; t < 4; t++)
            #pragma unroll
            for (int r = 0; r < 4; r++) ct[mi][t][r] = 0.0f;

    int   qz[4];
    float sE[4], sO[4];

    auto issue_cp = [&](int s) {
        const uint32_t dst0 = ws_b + (uint32_t)(s & (NBUF - 1)) * WSTAGE_B;
        const int* src0 = qweight + (size_t)(k0 + s * STAGE_K) * OUT_F + o0;
        #pragma unroll
        for (int j = 0; j < 4; j++) {
            int row = cp_row0 + 4 * j;
            uint32_t dst = dst0 + (uint32_t)row * WROW_B + (uint32_t)cp_seg * 16;
            const int* src = src0 + (size_t)row * OUT_F + cp_seg * 4;
            asm volatile("cp.async.cg.shared.global [%0], [%1], 16;" :: "r"(dst), "l"(src));
        }
        asm volatile("cp.async.commit_group;" ::: "memory");
    };

    // ---- prologue: 3 stages in flight ----
    issue_cp(0);
    issue_cp(1);
    issue_cp(2);

    for (int st = 0; st < NSTAGES; st++) {
        const int g  = st >> 3;                 // 8 stages per group of 128k
        const int gg = (k0 >> 7) + g;
        const int kb = k0 + g * GRP;

        // wait for stage st (keep younger in flight)
        if (st <= NSTAGES - 3)      asm volatile("cp.async.wait_group 2;" ::: "memory");
        else if (st == NSTAGES - 2) asm volatile("cp.async.wait_group 1;" ::: "memory");
        else                        asm volatile("cp.async.wait_group 0;" ::: "memory");
        __syncthreads();   // data visible; prior stage reads done (WAR for buffer reuse)

        if (st + 3 < NSTAGES) issue_cp(st + 3);

        // ---- group boundary: stage shared x tile + per-group constants ----
        if ((st & 7) == 0) {
            #pragma unroll
            for (int j = 0; j < 4; j++) {
                int idx = tid + THREADS * j;      // 0..1023
                int s   = idx >> 5;               // row 0..31
                int kq4 = idx & 31;
                float4 v = *(const float4*)(x + (size_t)s * IN_F + kb + 4 * kq4);
                uint32_t p0 = pack_bf16x2(v.y, v.x);
                uint32_t p1 = pack_bf16x2(v.w, v.z);
                uint32_t a = xs_b + (uint32_t)s * XROW_B + (uint32_t)kq4 * 8;
                asm volatile("st.shared.v2.b32 [%0], {%1,%2};" :: "r"(a), "r"(p0), "r"(p1));
            }
            #pragma unroll
            for (int t = 0; t < 4; t++) {
                qz[t] = qzeros[(size_t)gg * OUT_F + o0 + w * 32 + 8 * t + gid];
                sE[t] = bfr(scales[(size_t)gg * OUT_F + cc + 8 * t]);
                sO[t] = bfr(scales[(size_t)gg * OUT_F + cc + 8 * t + 1]);
            }
            __syncthreads();   // xs visible
        }

        const uint32_t rb = ws_b + (uint32_t)(st & (NBUF - 1)) * WSTAGE_B;

        // ---- one k16-step ----
        const int ks = st & 7;                   // kstep within group (xs index)
        uint32_t a0[4], a1[4];
        uint32_t addr0 = xs_b + a_lane_off + (uint32_t)ks * 32;
        uint32_t addr1 = addr0 + 16u * XROW_B;
        asm volatile("ldmatrix.sync.aligned.m8n8.x4.shared.b16 {%0,%1,%2,%3}, [%4];"
                     : "=r"(a0[0]), "=r"(a0[1]), "=r"(a0[2]), "=r"(a0[3]) : "r"(addr0));
        asm volatile("ldmatrix.sync.aligned.m8n8.x4.shared.b16 {%0,%1,%2,%3}, [%4];"
                     : "=r"(a1[0]), "=r"(a1[1]), "=r"(a1[2]), "=r"(a1[3]) : "r"(addr1));

        #pragma unroll
        for (int t = 0; t < 4; t++) {
            const uint32_t ba = rb + b_off + 32u * t;
            int v0, v1, v2, v3;
            asm volatile("ld.shared.b32 %0, [%1];" : "=r"(v0) : "r"(ba));
            asm volatile("ld.shared.b32 %0, [%1];" : "=r"(v1) : "r"(ba + WROW_B));
            asm volatile("ld.shared.b32 %0, [%1];" : "=r"(v2) : "r"(ba + 8 * WROW_B));
            asm volatile("ld.shared.b32 %0, [%1];" : "=r"(v3) : "r"(ba + 9 * WROW_B));
            uint32_t b0 = pack_bf16x2((float)(v1 - qz[t]), (float)(v0 - qz[t]));
            uint32_t b1 = pack_bf16x2((float)(v3 - qz[t]), (float)(v2 - qz[t]));

            float tmp[4];
            hmma0(tmp, a0, b0, b1);
            ct[0][t][0] = fmaf(tmp[0], sE[t], ct[0][t][0]);
            ct[0][t][1] = fmaf(tmp[1], sO[t], ct[0][t][1]);
            ct[0][t][2] = fmaf(tmp[2], sE[t], ct[0][t][2]);
            ct[0][t][3] = fmaf(tmp[3], sO[t], ct[0][t][3]);
            hmma0(tmp, a1, b0, b1);
            ct[1][t][0] = fmaf(tmp[0], sE[t], ct[1][t][0]);
            ct[1][t][1] = fmaf(tmp[1], sO[t], ct[1][t][1]);
            ct[1][t][2] = fmaf(tmp[2], sE[t], ct[1][t][2]);
            ct[1][t][3] = fmaf(tmp[3], sO[t], ct[1][t][3]);
        }
    }

    // ---- K-split reduction into bias-initialized output ----
    #pragma unroll
    for (int mi = 0; mi < 2; mi++) {
        int s0 = mi * 16 + gid;
        #pragma unroll
        for (int t = 0; t < 4; t++) {
            int oc = cc + t * 8;
            atomicAdd(&out[(size_t)s0 * OUT_F + oc],           ct[mi][t][0]);
            atomicAdd(&out[(size_t)s0 * OUT_F + oc + 1],       ct[mi][t][1]);
            atomicAdd(&out[(size_t)(s0 + 8) * OUT_F + oc],     ct[mi][t][2]);
            atomicAdd(&out[(size_t)(s0 + 8) * OUT_F + oc + 1], ct[mi][t][3]);
        }
    }
}

// ---------------------------------------------------------------------------
// inputs: x f32[1,32,4096], qweight i32[4096,11008], qzeros i32[32,11008],
//         scales f32[32,11008], bias f32[11008]; output f32[1,32,11008]
// ---------------------------------------------------------------------------
extern "C" void kernel_launch(void* const* d_in, const int* in_sizes, int n_in,
                              void* d_out, int out_size)
{
    const float* x       = (const float*)d_in[0];
    const int*   qweight = (const int*)  d_in[1];
    const int*   qzeros  = (const int*)  d_in[2];
    const float* scales  = (const float*)d_in[3];
    const float* bias    = (const float*)d_in[4];
    float*       out     = (float*)d_out;

    static int configured = 0;
    if (!configured) {
        cudaFuncSetAttribute(qmain, cudaFuncAttributeMaxDynamicSharedMemorySize, SM_TOTAL);
        configured = 1;
    }

    init_out_kernel<<<(OUT_F + 255) / 256, 256>>>(bias, out);
    qmain<<<CTAS_COL * KSPLIT, THREADS, SM_TOTAL>>>(x, qweight, qzeros, scales, out);
}

// round 13
// speedup vs baseline: 1.1782x; 1.1782x over previous
#include <cuda_runtime.h>
#include <cuda_bf16.h>
#include <cstdint>

#define IN_F     4096
#define OUT_F    11008
#define MROWS    32
#define GRP      128
#define KSPLIT   4
#define KPER     (IN_F / KSPLIT)          // 1024
#define STAGE_K  32
#define NSTAGES  (KPER / STAGE_K)         // 32
#define NBUF     4
#define NTILE    64
#define CTAS_COL (OUT_F / NTILE)          // 172
#define THREADS  128

#define XROW_B   272                      // x row: 256B bf16 + 16B pad (ldmatrix conflict-free)
#define WROW_B   272                      // W row: 64 int32 (256B) + 16B pad -> conflict-free LDS
#define WSTAGE_B (STAGE_K * WROW_B)       // 8704 per stage

__device__ __forceinline__ float bfr(float v) {
    return __bfloat162float(__float2bfloat16(v));
}

__device__ __forceinline__ uint32_t pack_bf16x2(float hi, float lo) {
    uint32_t r;
    asm("cvt.rn.bf16x2.f32 %0, %1, %2;" : "=r"(r) : "f"(hi), "f"(lo));
    return r;
}

__device__ __forceinline__ void hmma(float c[4], const uint32_t a[4],
                                     uint32_t b0, uint32_t b1) {
    asm volatile(
        "mma.sync.aligned.m16n8k16.row.col.f32.bf16.bf16.f32 "
        "{%0,%1,%2,%3}, {%4,%5,%6,%7}, {%8,%9}, {%0,%1,%2,%3};"
        : "+f"(c[0]), "+f"(c[1]), "+f"(c[2]), "+f"(c[3])
        : "r"(a[0]), "r"(a[1]), "r"(a[2]), "r"(a[3]), "r"(b0), "r"(b1));
}

// ---------------------------------------------------------------------------
__global__ void init_out_kernel(const float* __restrict__ bias,
                                float* __restrict__ out)
{
    int o = blockIdx.x * blockDim.x + threadIdx.x;
    if (o < OUT_F) {
        float b = bfr(bias[o]);
        #pragma unroll
        for (int s = 0; s < MROWS; s++)
            out[(size_t)s * OUT_F + o] = b;
    }
}

// ---------------------------------------------------------------------------
// R9 structure with a deeper ring: 64 output cols x 1024 K per CTA, raw int32
// qweight streamed via cp.async.cg into a 4-buffer ring of 32-row stages
// (3 in flight; same 43.5KB SMEM as R9's 2x64-row). B converts on-read
// ((qw-qz) 5-bit, bf16-exact); per-group scale in register epilogue (exact).
// ---------------------------------------------------------------------------
__global__ void __launch_bounds__(THREADS, 5)
qmain(const float* __restrict__ x, const int* __restrict__ qweight,
      const int* __restrict__ qzeros, const float* __restrict__ scales,
      float* __restrict__ out)
{
    __shared__ __align__(16) uint8_t xs_raw[MROWS * XROW_B];     //  8704 B
    __shared__ __align__(16) uint8_t ws_raw[NBUF * WSTAGE_B];    // 34816 B

    uint32_t xs_b, ws_b;
    asm("{ .reg .u64 t; cvta.to.shared.u64 t, %1; cvt.u32.u64 %0, t; }"
        : "=r"(xs_b) : "l"(xs_raw));
    asm("{ .reg .u64 t; cvta.to.shared.u64 t, %1; cvt.u32.u64 %0, t; }"
        : "=r"(ws_b) : "l"(ws_raw));

    const int tid   = threadIdx.x;
    const int w     = tid >> 5;
    const int l     = tid & 31;
    const int bx    = blockIdx.x;
    const int ctile = bx % CTAS_COL;
    const int kq    = bx / CTAS_COL;
    const int o0    = ctile * NTILE;
    const int k0    = kq * KPER;

    const int gid = l >> 2;
    const int tig = l & 3;
    const int nc0 = o0 + w * 16 + gid;      // B column, t=0
    const int nc1 = nc0 + 8;                // B column, t=1
    const int cc  = o0 + w * 16 + 2 * tig;  // C column base

    const uint32_t a_lane_off = (uint32_t)(l & 15) * XROW_B + (uint32_t)(l >> 4) * 16;
    const uint32_t b_off0 = (uint32_t)(2 * tig) * WROW_B + (uint32_t)(w * 16 + gid) * 4;
    const uint32_t b_off1 = b_off0 + 32;    // +8 cols

    // cp.async mapping: row = tid>>4 (+8j), seg = tid&15 (16B); 4 ops/thread
    const int cp_row0 = tid >> 4;
    const int cp_seg  = tid & 15;

    float ct[2][2][4], cg[2][2][4];
    #pragma unroll
    for (int mi = 0; mi < 2; mi++)
        #pragma unroll
        for (int t = 0; t < 2; t++)
            #pragma unroll
            for (int r = 0; r < 4; r++) { ct[mi][t][r] = 0.0f; cg[mi][t][r] = 0.0f; }

    int qz0 = 0, qz1 = 0;

    auto issue_cp = [&](int s) {
        const uint32_t dst0 = ws_b + (uint32_t)(s & (NBUF - 1)) * WSTAGE_B;
        const int* src0 = qweight + (size_t)(k0 + s * STAGE_K) * OUT_F + o0;
        #pragma unroll
        for (int j = 0; j < 4; j++) {
            int row = cp_row0 + 8 * j;
            uint32_t dst = dst0 + (uint32_t)row * WROW_B + (uint32_t)cp_seg * 16;
            const int* src = src0 + (size_t)row * OUT_F + cp_seg * 4;
            asm volatile("cp.async.cg.shared.global [%0], [%1], 16;" :: "r"(dst), "l"(src));
        }
        asm volatile("cp.async.commit_group;" ::: "memory");
    };

    // ---- prologue: 3 stages in flight ----
    issue_cp(0);
    issue_cp(1);
    issue_cp(2);

    for (int st = 0; st < NSTAGES; st++) {
        const int g  = st >> 2;                 // 4 stages per 128k group
        const int gg = (k0 >> 7) + g;
        const int kb = k0 + g * GRP;

        // wait for stage st (keep younger in flight)
        if (st <= NSTAGES - 3)      asm volatile("cp.async.wait_group 2;" ::: "memory");
        else if (st == NSTAGES - 2) asm volatile("cp.async.wait_group 1;" ::: "memory");
        else                        asm volatile("cp.async.wait_group 0;" ::: "memory");
        __syncthreads();   // copies visible to all; prior stage reads done (WAR)

        if (st + 3 < NSTAGES) issue_cp(st + 3);

        // ---- group boundary: stage shared x tile + per-group constants ----
        if ((st & 3) == 0) {
            #pragma unroll
            for (int j = 0; j < 8; j++) {
                int idx = tid + THREADS * j;      // 0..1023
                int s   = idx >> 5;               // row 0..31
                int kq4 = idx & 31;
                float4 v = *(const float4*)(x + (size_t)s * IN_F + kb + 4 * kq4);
                uint32_t p0 = pack_bf16x2(v.y, v.x);
                uint32_t p1 = pack_bf16x2(v.w, v.z);
                uint32_t a = xs_b + (uint32_t)s * XROW_B + (uint32_t)kq4 * 8;
                asm volatile("st.shared.v2.b32 [%0], {%1,%2};" :: "r"(a), "r"(p0), "r"(p1));
            }
            qz0 = qzeros[(size_t)gg * OUT_F + nc0];
            qz1 = qzeros[(size_t)gg * OUT_F + nc1];
            __syncthreads();   // xs visible
        }

        const uint32_t rbuf = ws_b + (uint32_t)(st & (NBUF - 1)) * WSTAGE_B;

        // ---- 2 k16-steps of this stage ----
        #pragma unroll
        for (int ksl = 0; ksl < 2; ksl++) {
            const int ks = 2 * (st & 3) + ksl;    // kstep within group (xs index)

            uint32_t a0[4], a1[4];
            uint32_t addr0 = xs_b + a_lane_off + (uint32_t)ks * 32;
            uint32_t addr1 = addr0 + 16u * XROW_B;
            asm volatile("ldmatrix.sync.aligned.m8n8.x4.shared.b16 {%0,%1,%2,%3}, [%4];"
                         : "=r"(a0[0]), "=r"(a0[1]), "=r"(a0[2]), "=r"(a0[3]) : "r"(addr0));
            asm volatile("ldmatrix.sync.aligned.m8n8.x4.shared.b16 {%0,%1,%2,%3}, [%4];"
                         : "=r"(a1[0]), "=r"(a1[1]), "=r"(a1[2]), "=r"(a1[3]) : "r"(addr1));

            const uint32_t rb = rbuf + (uint32_t)(16 * ksl) * WROW_B;

            {   // t = 0: rows 2tig, 2tig+1, 2tig+8, 2tig+9 at local col 16w+gid
                int v0, v1, v2, v3;
                asm volatile("ld.shared.b32 %0, [%1];" : "=r"(v0) : "r"(rb + b_off0));
                asm volatile("ld.shared.b32 %0, [%1];" : "=r"(v1) : "r"(rb + b_off0 + WROW_B));
                asm volatile("ld.shared.b32 %0, [%1];" : "=r"(v2) : "r"(rb + b_off0 + 8 * WROW_B));
                asm volatile("ld.shared.b32 %0, [%1];" : "=r"(v3) : "r"(rb + b_off0 + 9 * WROW_B));
                uint32_t b0 = pack_bf16x2((float)(v1 - qz0), (float)(v0 - qz0));
                uint32_t b1 = pack_bf16x2((float)(v3 - qz0), (float)(v2 - qz0));
                hmma(cg[0][0], a0, b0, b1);
                hmma(cg[1][0], a1, b0, b1);
            }
            {   // t = 1
                int v0, v1, v2, v3;
                asm volatile("ld.shared.b32 %0, [%1];" : "=r"(v0) : "r"(rb + b_off1));
                asm volatile("ld.shared.b32 %0, [%1];" : "=r"(v1) : "r"(rb + b_off1 + WROW_B));
                asm volatile("ld.shared.b32 %0, [%1];" : "=r"(v2) : "r"(rb + b_off1 + 8 * WROW_B));
                asm volatile("ld.shared.b32 %0, [%1];" : "=r"(v3) : "r"(rb + b_off1 + 9 * WROW_B));
                uint32_t b0 = pack_bf16x2((float)(v1 - qz1), (float)(v0 - qz1));
                uint32_t b1 = pack_bf16x2((float)(v3 - qz1), (float)(v2 - qz1));
                hmma(cg[0][1], a0, b0, b1);
                hmma(cg[1][1], a1, b0, b1);
            }
        }

        // ---- group done -> scale epilogue on C columns ----
        if ((st & 3) == 3) {
            const float sA = bfr(scales[(size_t)gg * OUT_F + cc]);
            const float sB = bfr(scales[(size_t)gg * OUT_F + cc + 1]);
            const float sC = bfr(scales[(size_t)gg * OUT_F + cc + 8]);
            const float sD = bfr(scales[(size_t)gg * OUT_F + cc + 9]);
            #pragma unroll
            for (int mi = 0; mi < 2; mi++) {
                ct[mi][0][0] = fmaf(cg[mi][0][0], sA, ct[mi][0][0]);
                ct[mi][0][1] = fmaf(cg[mi][0][1], sB, ct[mi][0][1]);
                ct[mi][0][2] = fmaf(cg[mi][0][2], sA, ct[mi][0][2]);
                ct[mi][0][3] = fmaf(cg[mi][0][3], sB, ct[mi][0][3]);
                ct[mi][1][0] = fmaf(cg[mi][1][0], sC, ct[mi][1][0]);
                ct[mi][1][1] = fmaf(cg[mi][1][1], sD, ct[mi][1][1]);
                ct[mi][1][2] = fmaf(cg[mi][1][2], sC, ct[mi][1][2]);
                ct[mi][1][3] = fmaf(cg[mi][1][3], sD, ct[mi][1][3]);
                #pragma unroll
                for (int t = 0; t < 2; t++)
                    #pragma unroll
                    for (int r = 0; r < 4; r++) cg[mi][t][r] = 0.0f;
            }
        }
    }

    // ---- K-split reduction into bias-initialized output ----
    #pragma unroll
    for (int mi = 0; mi < 2; mi++) {
        int s0 = mi * 16 + gid;
        #pragma unroll
        for (int t = 0; t < 2; t++) {
            int oc = cc + t * 8;
            atomicAdd(&out[(size_t)s0 * OUT_F + oc],           ct[mi][t][0]);
            atomicAdd(&out[(size_t)s0 * OUT_F + oc + 1],       ct[mi][t][1]);
            atomicAdd(&out[(size_t)(s0 + 8) * OUT_F + oc],     ct[mi][t][2]);
            atomicAdd(&out[(size_t)(s0 + 8) * OUT_F + oc + 1], ct[mi][t][3]);
        }
    }
}

// ---------------------------------------------------------------------------
// inputs: x f32[1,32,4096], qweight i32[4096,11008], qzeros i32[32,11008],
//         scales f32[32,11008], bias f32[11008]; output f32[1,32,11008]
// ---------------------------------------------------------------------------
extern "C" void kernel_launch(void* const* d_in, const int* in_sizes, int n_in,
                              void* d_out, int out_size)
{
    const float* x       = (const float*)d_in[0];
    const int*   qweight = (const int*)  d_in[1];
    const int*   qzeros  = (const int*)  d_in[2];
    const float* scales  = (const float*)d_in[3];
    const float* bias    = (const float*)d_in[4];
    float*       out     = (float*)d_out;

    init_out_kernel<<<(OUT_F + 255) / 256, 256>>>(bias, out);
    qmain<<<CTAS_COL * KSPLIT, THREADS>>>(x, qweight, qzeros, scales, out);
}